// round 4
// baseline (speedup 1.0000x reference)
#include <cuda_runtime.h>
#include <cuda_bf16.h>
#include <stdint.h>

// Rules_67619965108887: out[row, r] = f(x[i0])*f(x[5+i1])*f(x[10+i2]),
// r = i0*25 + i1*5 + i2, f(v) = (v==0)?1:v.
//
// R4 design (R3 post-mortem: barrier/latency-bound, not mem-bound):
//  Phase A: per-row factor tables in smem, built straight from gmem (L1 hits):
//           tp[row][j<25] = f(a[j/5]) * f(b[j%5]);  tp[row][25+k] = f(c[k])
//  (one barrier)
//  Phase B: flat float4 output walk. out[g..g+3] = tp[row][d] * tp[row][25+m]
//           with incremental (row,d,m) state -> ~6 instr/output, coalesced
//           aligned STG.128 (block spans 64 rows * 500B = 32000B ≡ 0 mod 16).

static constexpr int F = 15;
static constexpr int R = 125;
static constexpr int ROWS = 64;
static constexpr int THREADS = 256;

__global__ __launch_bounds__(THREADS)
void Rules_67619965108887_kernel(const float* __restrict__ x,
                                 float* __restrict__ out,
                                 int n_rows) {
    __shared__ float tp[ROWS][32];  // cols 0..24: p=a*b, cols 25..29: c, rest pad

    const int tid = threadIdx.x;
    const int row0 = blockIdx.x * ROWS;
    const int nrow = min(ROWS, n_rows - row0);

    // ---- Phase A: build tables (nrow*30 entries) ----
    const int nbuild = nrow * 30;
    const float* __restrict__ xb = x + (long long)row0 * F;
    for (int i = tid; i < nbuild; i += THREADS) {
        const int row = i / 30;
        const int j = i - row * 30;
        const float* __restrict__ xr = xb + row * F;
        float v;
        if (j < 25) {
            const int i0 = j / 5;
            const int i1 = j - i0 * 5;
            float a = __ldg(xr + i0);
            float b = __ldg(xr + 5 + i1);
            a = (a == 0.0f) ? 1.0f : a;
            b = (b == 0.0f) ? 1.0f : b;
            v = a * b;
        } else {
            float c = __ldg(xr + j - 15);  // 10 + (j-25)
            v = (c == 0.0f) ? 1.0f : c;
        }
        tp[row][j] = v;
    }
    __syncthreads();

    // ---- Phase B: coalesced float4 outputs ----
    const int ntot = nrow * R;          // 8000 for full block
    const int nf4 = ntot >> 2;          // 2000
    float4* __restrict__ o4 = (float4*)(out + (long long)row0 * R);

    for (int q = tid; q < nf4; q += THREADS) {
        const int g = q << 2;           // block-local flat output index
        int row = g / 125;              // reciprocal-mul, constant divisor
        int r = g - row * 125;
        int d = r / 5;
        int m = r - d * 5;

        float4 o;
        float* po = &o.x;
#pragma unroll
        for (int k = 0; k < 4; k++) {
            po[k] = tp[row][d] * tp[row][25 + m];
            // advance (row, d, m)
            if (++m == 5) {
                m = 0;
                if (++d == 25) { d = 0; ++row; }
            }
        }
        o4[q] = o;
    }

    // scalar tail (only if nrow*R not divisible by 4 — partial last block)
    for (int i = (nf4 << 2) + tid; i < ntot; i += THREADS) {
        const int row = i / 125;
        const int r = i - row * 125;
        const int d = r / 5;
        const int m = r - d * 5;
        out[(long long)row0 * R + i] = tp[row][d] * tp[row][25 + m];
    }
}

extern "C" void kernel_launch(void* const* d_in, const int* in_sizes, int n_in,
                              void* d_out, int out_size) {
    const float* x = (const float*)d_in[0];
    float* out = (float*)d_out;

    const int n_rows = in_sizes[0] / F;  // B*S = 32768
    const int grid = (n_rows + ROWS - 1) / ROWS;  // 512

    Rules_67619965108887_kernel<<<grid, THREADS>>>(x, out, n_rows);
}

// round 6
// speedup vs baseline: 1.7786x; 1.7786x over previous
#include <cuda_runtime.h>
#include <cuda_bf16.h>
#include <stdint.h>

// Rules_67619965108887: out[row, r] = f(x[i0])*f(x[5+i1])*f(x[10+i2]),
// r = i0*25 + i1*5 + i2, f(v) = (v==0)?1:v.
//
// R5: pure warp-shuffle kernel. No smem, no barriers. Warp-per-row,
// grid-stride. All lane-indexed constants hoisted out of the row loop:
//   p[j]   = f(x[j/5]) * f(x[5+j%5])   (lanes j=0..24, built with 2 SHFL)
//   pass t: out[row*125 + lane+32t] = shfl(p, d_t) * shfl(xv, 10+m_t)
// => ~26 warp-instructions per row of 125 outputs, coalesced STG.32.

static constexpr int F = 15;
static constexpr int R = 125;
static constexpr int THREADS = 256;
static constexpr unsigned FULL = 0xFFFFFFFFu;

__global__ __launch_bounds__(THREADS)
void Rules_67619965108887_kernel(const float* __restrict__ x,
                                 float* __restrict__ out,
                                 int n_rows) {
    const int lane = threadIdx.x & 31;
    const int gw   = (int)((blockIdx.x * blockDim.x + threadIdx.x) >> 5);
    const int nw   = (int)((gridDim.x * blockDim.x) >> 5);

    // ---- loop-invariant per-lane constants ----
    const int a_src = lane / 5;              // p-build: a lane (valid for lane<25)
    const int b_src = 5 + (lane - a_src * 5);  // p-build: b lane
    int d_t[4], c_src[4];
#pragma unroll
    for (int t = 0; t < 4; t++) {
        const int r = lane + 32 * t;
        const int d = r / 5;
        d_t[t]   = d;            // p source lane (valid while r < 125)
        c_src[t] = 10 + (r - d * 5);  // xv source lane for c
    }
    const bool last_ok = (lane < R - 96);  // pass 3 guard: r = lane+96 < 125

    int row = gw;
    if (row >= n_rows) return;

    // prefetch first row's value
    float xv_n = 1.0f;
    if (lane < F) xv_n = __ldg(x + (long long)row * F + lane);

    while (true) {
        float xv = (xv_n == 0.0f) ? 1.0f : xv_n;

        const int next = row + nw;
        if (next < n_rows) {                    // prefetch next row
            xv_n = 1.0f;
            if (lane < F) xv_n = __ldg(x + (long long)next * F + lane);
        }

        // p[lane] = f(a[lane/5]) * f(b[lane%5])  (meaningful on lanes 0..24)
        const float a = __shfl_sync(FULL, xv, a_src);
        const float b = __shfl_sync(FULL, xv, b_src);
        const float p = a * b;

        float* __restrict__ o = out + (long long)row * R + lane;

        {   // pass 0..2: all 32 lanes valid (r <= 95)
            const float P0 = __shfl_sync(FULL, p,  d_t[0]);
            const float C0 = __shfl_sync(FULL, xv, c_src[0]);
            o[0] = P0 * C0;
            const float P1 = __shfl_sync(FULL, p,  d_t[1]);
            const float C1 = __shfl_sync(FULL, xv, c_src[1]);
            o[32] = P1 * C1;
            const float P2 = __shfl_sync(FULL, p,  d_t[2]);
            const float C2 = __shfl_sync(FULL, xv, c_src[2]);
            o[64] = P2 * C2;
            const float P3 = __shfl_sync(FULL, p,  d_t[3]);
            const float C3 = __shfl_sync(FULL, xv, c_src[3]);
            if (last_ok) o[96] = P3 * C3;
        }

        if (next >= n_rows) break;
        row = next;
    }
}

extern "C" void kernel_launch(void* const* d_in, const int* in_sizes, int n_in,
                              void* d_out, int out_size) {
    const float* x = (const float*)d_in[0];
    float* out = (float*)d_out;

    const int n_rows = in_sizes[0] / F;  // B*S = 32768
    const int grid = 592;                // 148 SMs * 4 blocks -> 4736 warps

    Rules_67619965108887_kernel<<<grid, THREADS>>>(x, out, n_rows);
}